// round 11
// baseline (speedup 1.0000x reference)
#include <cuda_runtime.h>

#define NA 1024
#define NC 6
#define HH 48
#define NB_BINS 36
#define K_SP 1728          // 36*48
#define CE 64
#define VFC 16
#define OUT_C 128          // 64 + 16 + 48
#define M_ROWS (NA * NC)   // 6144
#define MAXE 512           // max supported episode size

typedef unsigned long long u64;

// ---- packed f32x2 helpers (Blackwell FFMA2 pipe) --------------------------
__device__ __forceinline__ u64 pack2(float lo, float hi) {
    u64 r; asm("mov.b64 %0, {%1,%2};" : "=l"(r) : "f"(lo), "f"(hi)); return r;
}
__device__ __forceinline__ u64 fma2(u64 a, u64 b, u64 c) {
    u64 d; asm("fma.rn.f32x2 %0, %1, %2, %3;" : "=l"(d) : "l"(a), "l"(b), "l"(c));
    return d;
}
__device__ __forceinline__ float2 unpack2(u64 v) {
    float2 f; asm("mov.b64 {%0,%1}, %2;" : "=f"(f.x), "=f"(f.y) : "l"(v)); return f;
}

// ---- device scratch -------------------------------------------------------
__device__ float g_hw[M_ROWS * K_SP];      // hW[row, bin*48+n]
__device__ int2  g_desc[M_ROWS * MAXE];    // per (row, agent): (offset, w bits)
__device__ int   g_esz[M_ROWS];            // episode size per row

// ---------------------------------------------------------------------------
// Kernel 1 (combined): blocks [0, 1728) = hW GEMM tiles (R5 hot loop);
// blocks [1728, 3264) = binning + fused concat (scene/vel) for 4 rows each.
// ---------------------------------------------------------------------------
#define PM 128
#define ASTRIDE (PM + 4)       // 132
#define NBLK_HW (M_ROWS / PM * NB_BINS)      // 1728
#define ROWS_PER_BINBLK 4
#define NBLK_BIN (M_ROWS / ROWS_PER_BINBLK)  // 1536
#define HW_SMEM_BYTES (HH * ASTRIDE * 4 + HH * HH * 4)   // 34560

__global__ void __launch_bounds__(256) hw_bin_kernel(
    const float* __restrict__ hidden,     // [M_ROWS, 48]
    const float* __restrict__ Ws,         // [1728, 48]
    const float* __restrict__ position,   // [M_ROWS, 2]
    const int*   __restrict__ ntt,        // [nb]
    const float* __restrict__ scene,      // [M_ROWS, 64]
    const float* __restrict__ velocity,   // [M_ROWS, 2]
    const float* __restrict__ Wv,         // [2, 16]
    const float* __restrict__ bv,         // [16]
    float* __restrict__ out,              // [M_ROWS, 128]
    int nb)
{
    __shared__ __align__(16) char sraw[HW_SMEM_BYTES];
    const int tid = threadIdx.x;

    if (blockIdx.x < NBLK_HW) {
        // ----------------- hW GEMM role (exact R5 body) --------------------
        float (*Asm)[ASTRIDE] = (float(*)[ASTRIDE])sraw;
        float (*Bsm)[HH]      = (float(*)[HH])(sraw + HH * ASTRIDE * 4);

        const int m0  = (blockIdx.x % (M_ROWS / PM)) * PM;
        const int bin = blockIdx.x / (M_ROWS / PM);

        for (int l = tid; l < (PM * HH) / 4; l += 256) {
            int m  = l / (HH / 4);
            int kq = (l % (HH / 4)) * 4;
            float4 v = *(const float4*)&hidden[(m0 + m) * HH + kq];
            Asm[kq + 0][m] = v.x;
            Asm[kq + 1][m] = v.y;
            Asm[kq + 2][m] = v.z;
            Asm[kq + 3][m] = v.w;
        }
        for (int l = tid; l < (HH * HH) / 4; l += 256) {
            int i = l / (HH / 4);
            int j = (l % (HH / 4)) * 4;
            *(float4*)&Bsm[i][j] = *(const float4*)&Ws[(bin * HH + i) * HH + j];
        }
        __syncthreads();

        const int ty = tid / 8;           // rows ty*4 .. ty*4+3
        const int tx = tid % 8;           // col pairs at tx*6 + {0,2,4}

        u64 acc[4][3];
#pragma unroll
        for (int r = 0; r < 4; r++)
#pragma unroll
            for (int p = 0; p < 3; p++) acc[r][p] = pack2(0.0f, 0.0f);

#pragma unroll 12
        for (int k = 0; k < HH; k++) {
            float4 a = *(const float4*)&Asm[k][ty * 4];
            u64 b0 = *(const u64*)&Bsm[k][tx * 6 + 0];
            u64 b1 = *(const u64*)&Bsm[k][tx * 6 + 2];
            u64 b2 = *(const u64*)&Bsm[k][tx * 6 + 4];
            u64 ad[4] = { pack2(a.x, a.x), pack2(a.y, a.y),
                          pack2(a.z, a.z), pack2(a.w, a.w) };
#pragma unroll
            for (int r = 0; r < 4; r++) {
                acc[r][0] = fma2(ad[r], b0, acc[r][0]);
                acc[r][1] = fma2(ad[r], b1, acc[r][1]);
                acc[r][2] = fma2(ad[r], b2, acc[r][2]);
            }
        }

#pragma unroll
        for (int r = 0; r < 4; r++) {
            int row = m0 + ty * 4 + r;
            float2* dst = (float2*)&g_hw[row * K_SP + bin * HH + tx * 6];
            dst[0] = unpack2(acc[r][0]);
            dst[1] = unpack2(acc[r][1]);
            dst[2] = unpack2(acc[r][2]);
        }
    } else {
        // ------------- binning + concat role: 4 rows per block -------------
        int*   s_bin = (int*)sraw;                         // [4][MAXE]
        int*   s_cnt = (int*)(sraw + 4 * MAXE * 4);        // [4][36]
        float* s_inv = (float*)(sraw + 4 * MAXE * 4 + 4 * NB_BINS * 4);

        const int base = (blockIdx.x - NBLK_HW) * ROWS_PER_BINBLK;
        const int sub  = tid / 64;        // 0..3
        const int lane = tid % 64;
        const int row  = base + sub;
        const int a = row / NC;
        const int c = row % NC;

        if (lane < NB_BINS) s_cnt[sub * NB_BINS + lane] = 0;

        int start = 0, end = 0, cum = 0;
        for (int i = 0; i < nb; i++) {
            int s = ntt[i];
            if (a >= cum && a < cum + s) { start = cum; end = cum + s; }
            cum += s;
        }
        int esz = end - start;
        if (esz > MAXE) esz = MAXE;

        const float px = position[row * 2 + 0];
        const float py = position[row * 2 + 1];
        const float rlogf = 0.34657359027997264f;
        const float PIf   = 3.14159265358979323846f;

        // fused concat (independent of binning): scene cols [0,64)
        out[row * OUT_C + lane] = scene[row * CE + lane];
        // velocity encoder cols [64,80)
        if (lane < VFC) {
            float v = velocity[row * 2 + 0] * Wv[lane]
                    + velocity[row * 2 + 1] * Wv[VFC + lane] + bv[lane];
            out[row * OUT_C + CE + lane] = fmaxf(v, 0.0f);
        }

        __syncthreads();

        for (int b = lane; b < esz; b += 64) {
            int brow = (start + b) * NC + c;
            float xd = px - position[brow * 2 + 0];
            float yd = py - position[brow * 2 + 1];
            float dist = sqrtf(xd * xd + yd * yd);
            int ring = (int)floorf(logf(dist / 0.5f + 1e-6f) / rlogf);
            int bin = -1;
            if (ring >= 0 && ring < 6) {
                float theta = atan2f(yd, xd);
                int wedge = (int)floorf((theta + PIf - 1e-6f) / PIf / 2.0f * 6.0f);
                bin = ring * 6 + wedge;
                if (bin < 0 || bin >= NB_BINS) bin = -1;
            }
            s_bin[sub * MAXE + b] = bin;
            if (bin >= 0) atomicAdd(&s_cnt[sub * NB_BINS + bin], 1);
        }
        __syncthreads();
        if (lane < NB_BINS)
            s_inv[sub * NB_BINS + lane] =
                1.0f / (float)max(s_cnt[sub * NB_BINS + lane], 1);
        __syncthreads();

        for (int b = lane; b < esz; b += 64) {
            int bin = s_bin[sub * MAXE + b];
            int off = ((start + b) * NC + c) * K_SP + max(bin, 0) * HH;
            float w = (bin >= 0) ? s_inv[sub * NB_BINS + bin] : 0.0f;
            g_desc[row * MAXE + b] = make_int2(off, __float_as_int(w));
        }
        if (lane == 0) g_esz[row] = esz;
    }
}

// ---------------------------------------------------------------------------
// Kernel 2: slim gather — descriptors -> smem, 4-way unrolled multi-acc sum
// (MLP≈4 per thread), bias + relu.
// ---------------------------------------------------------------------------
__global__ void __launch_bounds__(192) gather_kernel(
    const float* __restrict__ bs,         // [48]
    float* __restrict__ out)              // [M_ROWS, 128]
{
    const int row = blockIdx.x;
    const int tid = threadIdx.x;

    __shared__ int2  s_ow[MAXE];
    __shared__ float s_red[4][HH];

    const int esz = g_esz[row];
    for (int l = tid; l < esz; l += 192)
        s_ow[l] = g_desc[row * MAXE + l];
    __syncthreads();

    // gather-sum (4 groups x 48 cols), unrolled x4 with indep accumulators
    const int bq = tid / HH;              // 0..3
    const int n  = tid % HH;
    float a0 = 0.0f, a1 = 0.0f, a2 = 0.0f, a3 = 0.0f;
    int b = bq;
    for (; b + 12 < esz; b += 16) {
        int2 q0 = s_ow[b];
        int2 q1 = s_ow[b + 4];
        int2 q2 = s_ow[b + 8];
        int2 q3 = s_ow[b + 12];
        float v0 = g_hw[q0.x + n];
        float v1 = g_hw[q1.x + n];
        float v2 = g_hw[q2.x + n];
        float v3 = g_hw[q3.x + n];
        a0 += v0 * __int_as_float(q0.y);
        a1 += v1 * __int_as_float(q1.y);
        a2 += v2 * __int_as_float(q2.y);
        a3 += v3 * __int_as_float(q3.y);
    }
    for (; b < esz; b += 4) {
        int2 q = s_ow[b];
        a0 += g_hw[q.x + n] * __int_as_float(q.y);
    }
    s_red[bq][n] = (a0 + a1) + (a2 + a3);
    __syncthreads();

    // final reduce + bias + relu -> cols [80,128)
    if (tid < HH) {
        float t = s_red[0][tid] + s_red[1][tid] + s_red[2][tid] + s_red[3][tid];
        out[row * OUT_C + CE + VFC + tid] = fmaxf(t + bs[tid], 0.0f);
    }
}

// ---------------------------------------------------------------------------
extern "C" void kernel_launch(void* const* d_in, const int* in_sizes, int n_in,
                              void* d_out, int out_size)
{
    const float* hidden   = (const float*)d_in[0];
    const float* velocity = (const float*)d_in[1];
    const float* position = (const float*)d_in[2];
    const float* scene    = (const float*)d_in[3];
    const int*   ntt      = (const int*)d_in[4];
    const float* Wv       = (const float*)d_in[5];
    const float* bv       = (const float*)d_in[6];
    const float* Ws       = (const float*)d_in[7];
    const float* bs       = (const float*)d_in[8];
    float* out = (float*)d_out;
    int nb = in_sizes[4];

    hw_bin_kernel<<<NBLK_HW + NBLK_BIN, 256>>>(hidden, Ws, position, ntt,
                                               scene, velocity, Wv, bv, out, nb);
    gather_kernel<<<M_ROWS, 192>>>(bs, out);
}

// round 12
// speedup vs baseline: 1.0376x; 1.0376x over previous
#include <cuda_runtime.h>

#define NA 1024
#define NC 6
#define HH 48
#define NB_BINS 36
#define K_SP 1728          // 36*48
#define CE 64
#define VFC 16
#define OUT_C 128          // 64 + 16 + 48
#define M_ROWS (NA * NC)   // 6144
#define MAXE 512           // max supported episode size

typedef unsigned long long u64;

// ---- packed f32x2 helpers (Blackwell FFMA2 pipe) --------------------------
__device__ __forceinline__ u64 pack2(float lo, float hi) {
    u64 r; asm("mov.b64 %0, {%1,%2};" : "=l"(r) : "f"(lo), "f"(hi)); return r;
}
__device__ __forceinline__ u64 fma2(u64 a, u64 b, u64 c) {
    u64 d; asm("fma.rn.f32x2 %0, %1, %2, %3;" : "=l"(d) : "l"(a), "l"(b), "l"(c));
    return d;
}
__device__ __forceinline__ float2 unpack2(u64 v) {
    float2 f; asm("mov.b64 {%0,%1}, %2;" : "=f"(f.x), "=f"(f.y) : "l"(v)); return f;
}

// ---- device scratch -------------------------------------------------------
__device__ float g_hw[M_ROWS * K_SP];      // hW[row, bin*48+n]
__device__ int2  g_desc[M_ROWS * MAXE];    // per (row, agent): (offset, w bits)
__device__ int   g_esz[M_ROWS];            // episode size per row

// ---------------------------------------------------------------------------
// Kernel 1 (combined): blocks [0, 1728) = hW GEMM tiles (R5 hot loop);
// blocks [1728, 3264) = binning + fused concat (scene/vel) for 4 rows each.
// (unchanged from R10/R11 — measured ~34.5us)
// ---------------------------------------------------------------------------
#define PM 128
#define ASTRIDE (PM + 4)       // 132
#define NBLK_HW (M_ROWS / PM * NB_BINS)      // 1728
#define ROWS_PER_BINBLK 4
#define NBLK_BIN (M_ROWS / ROWS_PER_BINBLK)  // 1536
#define HW_SMEM_BYTES (HH * ASTRIDE * 4 + HH * HH * 4)   // 34560

__global__ void __launch_bounds__(256) hw_bin_kernel(
    const float* __restrict__ hidden,     // [M_ROWS, 48]
    const float* __restrict__ Ws,         // [1728, 48]
    const float* __restrict__ position,   // [M_ROWS, 2]
    const int*   __restrict__ ntt,        // [nb]
    const float* __restrict__ scene,      // [M_ROWS, 64]
    const float* __restrict__ velocity,   // [M_ROWS, 2]
    const float* __restrict__ Wv,         // [2, 16]
    const float* __restrict__ bv,         // [16]
    float* __restrict__ out,              // [M_ROWS, 128]
    int nb)
{
    __shared__ __align__(16) char sraw[HW_SMEM_BYTES];
    const int tid = threadIdx.x;

    if (blockIdx.x < NBLK_HW) {
        // ----------------- hW GEMM role (exact R5 body) --------------------
        float (*Asm)[ASTRIDE] = (float(*)[ASTRIDE])sraw;
        float (*Bsm)[HH]      = (float(*)[HH])(sraw + HH * ASTRIDE * 4);

        const int m0  = (blockIdx.x % (M_ROWS / PM)) * PM;
        const int bin = blockIdx.x / (M_ROWS / PM);

        for (int l = tid; l < (PM * HH) / 4; l += 256) {
            int m  = l / (HH / 4);
            int kq = (l % (HH / 4)) * 4;
            float4 v = *(const float4*)&hidden[(m0 + m) * HH + kq];
            Asm[kq + 0][m] = v.x;
            Asm[kq + 1][m] = v.y;
            Asm[kq + 2][m] = v.z;
            Asm[kq + 3][m] = v.w;
        }
        for (int l = tid; l < (HH * HH) / 4; l += 256) {
            int i = l / (HH / 4);
            int j = (l % (HH / 4)) * 4;
            *(float4*)&Bsm[i][j] = *(const float4*)&Ws[(bin * HH + i) * HH + j];
        }
        __syncthreads();

        const int ty = tid / 8;           // rows ty*4 .. ty*4+3
        const int tx = tid % 8;           // col pairs at tx*6 + {0,2,4}

        u64 acc[4][3];
#pragma unroll
        for (int r = 0; r < 4; r++)
#pragma unroll
            for (int p = 0; p < 3; p++) acc[r][p] = pack2(0.0f, 0.0f);

#pragma unroll 12
        for (int k = 0; k < HH; k++) {
            float4 a = *(const float4*)&Asm[k][ty * 4];
            u64 b0 = *(const u64*)&Bsm[k][tx * 6 + 0];
            u64 b1 = *(const u64*)&Bsm[k][tx * 6 + 2];
            u64 b2 = *(const u64*)&Bsm[k][tx * 6 + 4];
            u64 ad[4] = { pack2(a.x, a.x), pack2(a.y, a.y),
                          pack2(a.z, a.z), pack2(a.w, a.w) };
#pragma unroll
            for (int r = 0; r < 4; r++) {
                acc[r][0] = fma2(ad[r], b0, acc[r][0]);
                acc[r][1] = fma2(ad[r], b1, acc[r][1]);
                acc[r][2] = fma2(ad[r], b2, acc[r][2]);
            }
        }

#pragma unroll
        for (int r = 0; r < 4; r++) {
            int row = m0 + ty * 4 + r;
            float2* dst = (float2*)&g_hw[row * K_SP + bin * HH + tx * 6];
            dst[0] = unpack2(acc[r][0]);
            dst[1] = unpack2(acc[r][1]);
            dst[2] = unpack2(acc[r][2]);
        }
    } else {
        // ------------- binning + concat role: 4 rows per block -------------
        int*   s_bin = (int*)sraw;                         // [4][MAXE]
        int*   s_cnt = (int*)(sraw + 4 * MAXE * 4);        // [4][36]
        float* s_inv = (float*)(sraw + 4 * MAXE * 4 + 4 * NB_BINS * 4);

        const int base = (blockIdx.x - NBLK_HW) * ROWS_PER_BINBLK;
        const int sub  = tid / 64;        // 0..3
        const int lane = tid % 64;
        const int row  = base + sub;
        const int a = row / NC;
        const int c = row % NC;

        if (lane < NB_BINS) s_cnt[sub * NB_BINS + lane] = 0;

        int start = 0, end = 0, cum = 0;
        for (int i = 0; i < nb; i++) {
            int s = ntt[i];
            if (a >= cum && a < cum + s) { start = cum; end = cum + s; }
            cum += s;
        }
        int esz = end - start;
        if (esz > MAXE) esz = MAXE;

        const float px = position[row * 2 + 0];
        const float py = position[row * 2 + 1];
        const float rlogf = 0.34657359027997264f;
        const float PIf   = 3.14159265358979323846f;

        // fused concat (independent of binning): scene cols [0,64)
        out[row * OUT_C + lane] = scene[row * CE + lane];
        // velocity encoder cols [64,80)
        if (lane < VFC) {
            float v = velocity[row * 2 + 0] * Wv[lane]
                    + velocity[row * 2 + 1] * Wv[VFC + lane] + bv[lane];
            out[row * OUT_C + CE + lane] = fmaxf(v, 0.0f);
        }

        __syncthreads();

        for (int b = lane; b < esz; b += 64) {
            int brow = (start + b) * NC + c;
            float xd = px - position[brow * 2 + 0];
            float yd = py - position[brow * 2 + 1];
            float dist = sqrtf(xd * xd + yd * yd);
            int ring = (int)floorf(logf(dist / 0.5f + 1e-6f) / rlogf);
            int bin = -1;
            if (ring >= 0 && ring < 6) {
                float theta = atan2f(yd, xd);
                int wedge = (int)floorf((theta + PIf - 1e-6f) / PIf / 2.0f * 6.0f);
                bin = ring * 6 + wedge;
                if (bin < 0 || bin >= NB_BINS) bin = -1;
            }
            s_bin[sub * MAXE + b] = bin;
            if (bin >= 0) atomicAdd(&s_cnt[sub * NB_BINS + bin], 1);
        }
        __syncthreads();
        if (lane < NB_BINS)
            s_inv[sub * NB_BINS + lane] =
                1.0f / (float)max(s_cnt[sub * NB_BINS + lane], 1);
        __syncthreads();

        for (int b = lane; b < esz; b += 64) {
            int bin = s_bin[sub * MAXE + b];
            int off = ((start + b) * NC + c) * K_SP + max(bin, 0) * HH;
            float w = (bin >= 0) ? s_inv[sub * NB_BINS + bin] : 0.0f;
            g_desc[row * MAXE + b] = make_int2(off, __float_as_int(w));
        }
        if (lane == 0) g_esz[row] = esz;
    }
}

// ---------------------------------------------------------------------------
// Kernel 2: slim gather — descriptors -> smem, then 16 groups x 12 threads
// x float4 cols: per agent row 12 x LDG.128 instead of 48 x LDG.32.
// ---------------------------------------------------------------------------
__global__ void __launch_bounds__(192) gather_kernel(
    const float* __restrict__ bs,         // [48]
    float* __restrict__ out)              // [M_ROWS, 128]
{
    const int row = blockIdx.x;
    const int tid = threadIdx.x;

    __shared__ int2  s_ow[MAXE];
    __shared__ float s_red[16][HH];

    const int esz = g_esz[row];
    for (int l = tid; l < esz; l += 192)
        s_ow[l] = g_desc[row * MAXE + l];
    __syncthreads();

    // gather-sum: 16 agent-groups x 12 threads x 4 cols (LDG.128)
    const int g  = tid / 12;              // 0..15
    const int n0 = (tid % 12) * 4;        // 16B-aligned col quad
    float4 acc0 = make_float4(0.f, 0.f, 0.f, 0.f);
    float4 acc1 = make_float4(0.f, 0.f, 0.f, 0.f);
    int b = g;
    for (; b + 16 < esz; b += 32) {
        int2 q0 = s_ow[b];
        int2 q1 = s_ow[b + 16];
        float4 v0 = *(const float4*)&g_hw[q0.x + n0];
        float4 v1 = *(const float4*)&g_hw[q1.x + n0];
        float w0 = __int_as_float(q0.y);
        float w1 = __int_as_float(q1.y);
        acc0.x += v0.x * w0; acc0.y += v0.y * w0;
        acc0.z += v0.z * w0; acc0.w += v0.w * w0;
        acc1.x += v1.x * w1; acc1.y += v1.y * w1;
        acc1.z += v1.z * w1; acc1.w += v1.w * w1;
    }
    for (; b < esz; b += 16) {
        int2 q = s_ow[b];
        float4 v = *(const float4*)&g_hw[q.x + n0];
        float w = __int_as_float(q.y);
        acc0.x += v.x * w; acc0.y += v.y * w;
        acc0.z += v.z * w; acc0.w += v.w * w;
    }
    s_red[g][n0 + 0] = acc0.x + acc1.x;
    s_red[g][n0 + 1] = acc0.y + acc1.y;
    s_red[g][n0 + 2] = acc0.z + acc1.z;
    s_red[g][n0 + 3] = acc0.w + acc1.w;
    __syncthreads();

    // final reduce + bias + relu -> cols [80,128)
    if (tid < HH) {
        float t = 0.0f;
#pragma unroll
        for (int p = 0; p < 16; p++) t += s_red[p][tid];
        out[row * OUT_C + CE + VFC + tid] = fmaxf(t + bs[tid], 0.0f);
    }
}

// ---------------------------------------------------------------------------
extern "C" void kernel_launch(void* const* d_in, const int* in_sizes, int n_in,
                              void* d_out, int out_size)
{
    const float* hidden   = (const float*)d_in[0];
    const float* velocity = (const float*)d_in[1];
    const float* position = (const float*)d_in[2];
    const float* scene    = (const float*)d_in[3];
    const int*   ntt      = (const int*)d_in[4];
    const float* Wv       = (const float*)d_in[5];
    const float* bv       = (const float*)d_in[6];
    const float* Ws       = (const float*)d_in[7];
    const float* bs       = (const float*)d_in[8];
    float* out = (float*)d_out;
    int nb = in_sizes[4];

    hw_bin_kernel<<<NBLK_HW + NBLK_BIN, 256>>>(hidden, Ws, position, ntt,
                                               scene, velocity, Wv, bv, out, nb);
    gather_kernel<<<M_ROWS, 192>>>(bs, out);
}

// round 15
// speedup vs baseline: 1.2156x; 1.1715x over previous
#include <cuda_runtime.h>
#include <cstdint>

#define NA 1024
#define NC 6
#define HH 48
#define NB_BINS 36
#define K_SP 1728          // 36*48
#define CE 64
#define VFC 16
#define OUT_C 128          // 64 + 16 + 48
#define M_ROWS (NA * NC)   // 6144
#define MAXE 512           // max supported episode size

// ---- device scratch -------------------------------------------------------
__device__ float g_hw[M_ROWS * K_SP];      // hW[row, bin*48+n]
__device__ int2  g_desc[M_ROWS * MAXE];    // per (row, agent): (offset, w bits)
__device__ int   g_esz[M_ROWS];            // episode size per row

// ---- tf32 helpers ---------------------------------------------------------
// NOTE: tf32 cvt destination must be a b32 register (ptxas rejects .f32 dst).
__device__ __forceinline__ uint32_t to_tf32(float x) {
    uint32_t y; asm("cvt.rna.tf32.f32 %0, %1;" : "=r"(y) : "f"(x)); return y;
}
__device__ __forceinline__ void mma_tf32(float4& d,
    uint32_t a0, uint32_t a1, uint32_t a2, uint32_t a3,
    uint32_t b0, uint32_t b1)
{
    asm volatile(
        "mma.sync.aligned.m16n8k8.row.col.f32.tf32.tf32.f32 "
        "{%0,%1,%2,%3}, {%4,%5,%6,%7}, {%8,%9}, {%0,%1,%2,%3};"
        : "+f"(d.x), "+f"(d.y), "+f"(d.z), "+f"(d.w)
        : "r"(a0), "r"(a1), "r"(a2), "r"(a3), "r"(b0), "r"(b1));
}

// ---------------------------------------------------------------------------
// Kernel 1 (combined): blocks [0, 1728) = hW GEMM tiles via tf32 mma.sync;
// blocks [1728, 3264) = binning + fused concat (scene/vel) for 4 rows each.
// ---------------------------------------------------------------------------
#define PM 128
#define SSTRIDE 52            // smem row stride (floats); conflict-free frags
#define NBLK_HW (M_ROWS / PM * NB_BINS)      // 1728
#define ROWS_PER_BINBLK 4
#define NBLK_BIN (M_ROWS / ROWS_PER_BINBLK)  // 1536
#define HW_SMEM_BYTES ((PM * SSTRIDE + HH * SSTRIDE) * 4)   // 36608

__global__ void __launch_bounds__(256) hw_bin_kernel(
    const float* __restrict__ hidden,     // [M_ROWS, 48]
    const float* __restrict__ Ws,         // [1728, 48]
    const float* __restrict__ position,   // [M_ROWS, 2]
    const int*   __restrict__ ntt,        // [nb]
    const float* __restrict__ scene,      // [M_ROWS, 64]
    const float* __restrict__ velocity,   // [M_ROWS, 2]
    const float* __restrict__ Wv,         // [2, 16]
    const float* __restrict__ bv,         // [16]
    float* __restrict__ out,              // [M_ROWS, 128]
    int nb)
{
    __shared__ __align__(16) char sraw[HW_SMEM_BYTES];
    const int tid = threadIdx.x;

    if (blockIdx.x < NBLK_HW) {
        // ------------- hW GEMM role: tf32 tensor cores ---------------------
        uint32_t (*As)[SSTRIDE] = (uint32_t(*)[SSTRIDE])sraw;                   // [128][52]
        uint32_t (*Bs)[SSTRIDE] = (uint32_t(*)[SSTRIDE])(sraw + PM * SSTRIDE * 4); // [48][52]

        const int m0  = (blockIdx.x % (M_ROWS / PM)) * PM;
        const int bin = blockIdx.x / (M_ROWS / PM);

        // stage A [128 x 48] (tf32-rounded bits)
        for (int l = tid; l < PM * (HH / 4); l += 256) {
            int row = l / (HH / 4);
            int q   = (l % (HH / 4)) * 4;
            float4 v = *(const float4*)&hidden[(m0 + row) * HH + q];
            As[row][q + 0] = to_tf32(v.x);
            As[row][q + 1] = to_tf32(v.y);
            As[row][q + 2] = to_tf32(v.z);
            As[row][q + 3] = to_tf32(v.w);
        }
        // stage B block: W_b[k][n] = Ws[bin*48+k][n] (tf32-rounded bits)
        for (int l = tid; l < HH * (HH / 4); l += 256) {
            int k = l / (HH / 4);
            int q = (l % (HH / 4)) * 4;
            float4 v = *(const float4*)&Ws[(bin * HH + k) * HH + q];
            Bs[k][q + 0] = to_tf32(v.x);
            Bs[k][q + 1] = to_tf32(v.y);
            Bs[k][q + 2] = to_tf32(v.z);
            Bs[k][q + 3] = to_tf32(v.w);
        }
        __syncthreads();

        const int w    = tid / 32;        // warp 0..7 -> rows w*16..w*16+15
        const int lane = tid % 32;
        const int r    = lane >> 2;       // 0..7
        const int cc   = lane & 3;        // 0..3
        const int w16  = w * 16;

        // hoist all 6 A k-fragments (24 regs)
        uint32_t af[6][4];
#pragma unroll
        for (int t = 0; t < 6; t++) {
            af[t][0] = As[w16 + r    ][8 * t + cc    ];
            af[t][1] = As[w16 + r + 8][8 * t + cc    ];
            af[t][2] = As[w16 + r    ][8 * t + cc + 4];
            af[t][3] = As[w16 + r + 8][8 * t + cc + 4];
        }

#pragma unroll
        for (int j = 0; j < 6; j++) {     // n-tiles of 8
            float4 d = make_float4(0.f, 0.f, 0.f, 0.f);
#pragma unroll
            for (int t = 0; t < 6; t++) { // k-tiles of 8
                uint32_t b0 = Bs[8 * t + cc    ][8 * j + r];
                uint32_t b1 = Bs[8 * t + cc + 4][8 * j + r];
                mma_tf32(d, af[t][0], af[t][1], af[t][2], af[t][3], b0, b1);
            }
            // write D fragment
            int colb = bin * HH + 8 * j + 2 * cc;
            float* p0 = &g_hw[(m0 + w16 + r    ) * K_SP + colb];
            float* p1 = &g_hw[(m0 + w16 + r + 8) * K_SP + colb];
            p0[0] = d.x; p0[1] = d.y;
            p1[0] = d.z; p1[1] = d.w;
        }
    } else {
        // ------------- binning + concat role: 4 rows per block -------------
        int*   s_bin = (int*)sraw;                         // [4][MAXE]
        int*   s_cnt = (int*)(sraw + 4 * MAXE * 4);        // [4][36]
        float* s_inv = (float*)(sraw + 4 * MAXE * 4 + 4 * NB_BINS * 4);

        const int base = (blockIdx.x - NBLK_HW) * ROWS_PER_BINBLK;
        const int sub  = tid / 64;        // 0..3
        const int lane = tid % 64;
        const int row  = base + sub;
        const int a = row / NC;
        const int c = row % NC;

        if (lane < NB_BINS) s_cnt[sub * NB_BINS + lane] = 0;

        int start = 0, end = 0, cum = 0;
        for (int i = 0; i < nb; i++) {
            int s = ntt[i];
            if (a >= cum && a < cum + s) { start = cum; end = cum + s; }
            cum += s;
        }
        int esz = end - start;
        if (esz > MAXE) esz = MAXE;

        const float px = position[row * 2 + 0];
        const float py = position[row * 2 + 1];
        const float rlogf = 0.34657359027997264f;
        const float PIf   = 3.14159265358979323846f;

        // fused concat (independent of binning): scene cols [0,64)
        out[row * OUT_C + lane] = scene[row * CE + lane];
        // velocity encoder cols [64,80)
        if (lane < VFC) {
            float v = velocity[row * 2 + 0] * Wv[lane]
                    + velocity[row * 2 + 1] * Wv[VFC + lane] + bv[lane];
            out[row * OUT_C + CE + lane] = fmaxf(v, 0.0f);
        }

        __syncthreads();

        for (int b = lane; b < esz; b += 64) {
            int brow = (start + b) * NC + c;
            float xd = px - position[brow * 2 + 0];
            float yd = py - position[brow * 2 + 1];
            float dist = sqrtf(xd * xd + yd * yd);
            int ring = (int)floorf(logf(dist / 0.5f + 1e-6f) / rlogf);
            int bin = -1;
            if (ring >= 0 && ring < 6) {
                float theta = atan2f(yd, xd);
                int wedge = (int)floorf((theta + PIf - 1e-6f) / PIf / 2.0f * 6.0f);
                bin = ring * 6 + wedge;
                if (bin < 0 || bin >= NB_BINS) bin = -1;
            }
            s_bin[sub * MAXE + b] = bin;
            if (bin >= 0) atomicAdd(&s_cnt[sub * NB_BINS + bin], 1);
        }
        __syncthreads();
        if (lane < NB_BINS)
            s_inv[sub * NB_BINS + lane] =
                1.0f / (float)max(s_cnt[sub * NB_BINS + lane], 1);
        __syncthreads();

        for (int b = lane; b < esz; b += 64) {
            int bin = s_bin[sub * MAXE + b];
            int off = ((start + b) * NC + c) * K_SP + max(bin, 0) * HH;
            float w = (bin >= 0) ? s_inv[sub * NB_BINS + bin] : 0.0f;
            g_desc[row * MAXE + b] = make_int2(off, __float_as_int(w));
        }
        if (lane == 0) g_esz[row] = esz;
    }
}

// ---------------------------------------------------------------------------
// Kernel 2: slim gather (R12 version, measured 19.3us) — descriptors ->
// smem, 16 groups x 12 threads x float4 cols (LDG.128).
// ---------------------------------------------------------------------------
__global__ void __launch_bounds__(192) gather_kernel(
    const float* __restrict__ bs,         // [48]
    float* __restrict__ out)              // [M_ROWS, 128]
{
    const int row = blockIdx.x;
    const int tid = threadIdx.x;

    __shared__ int2  s_ow[MAXE];
    __shared__ float s_red[16][HH];

    const int esz = g_esz[row];
    for (int l = tid; l < esz; l += 192)
        s_ow[l] = g_desc[row * MAXE + l];
    __syncthreads();

    const int g  = tid / 12;              // 0..15
    const int n0 = (tid % 12) * 4;        // 16B-aligned col quad
    float4 acc0 = make_float4(0.f, 0.f, 0.f, 0.f);
    float4 acc1 = make_float4(0.f, 0.f, 0.f, 0.f);
    int b = g;
    for (; b + 16 < esz; b += 32) {
        int2 q0 = s_ow[b];
        int2 q1 = s_ow[b + 16];
        float4 v0 = *(const float4*)&g_hw[q0.x + n0];
        float4 v1 = *(const float4*)&g_hw[q1.x + n0];
        float w0 = __int_as_float(q0.y);
        float w1 = __int_as_float(q1.y);
        acc0.x += v0.x * w0; acc0.y += v0.y * w0;
        acc0.z += v0.z * w0; acc0.w += v0.w * w0;
        acc1.x += v1.x * w1; acc1.y += v1.y * w1;
        acc1.z += v1.z * w1; acc1.w += v1.w * w1;
    }
    for (; b < esz; b += 16) {
        int2 q = s_ow[b];
        float4 v = *(const float4*)&g_hw[q.x + n0];
        float w = __int_as_float(q.y);
        acc0.x += v.x * w; acc0.y += v.y * w;
        acc0.z += v.z * w; acc0.w += v.w * w;
    }
    s_red[g][n0 + 0] = acc0.x + acc1.x;
    s_red[g][n0 + 1] = acc0.y + acc1.y;
    s_red[g][n0 + 2] = acc0.z + acc1.z;
    s_red[g][n0 + 3] = acc0.w + acc1.w;
    __syncthreads();

    if (tid < HH) {
        float t = 0.0f;
#pragma unroll
        for (int p = 0; p < 16; p++) t += s_red[p][tid];
        out[row * OUT_C + CE + VFC + tid] = fmaxf(t + bs[tid], 0.0f);
    }
}

// ---------------------------------------------------------------------------
extern "C" void kernel_launch(void* const* d_in, const int* in_sizes, int n_in,
                              void* d_out, int out_size)
{
    const float* hidden   = (const float*)d_in[0];
    const float* velocity = (const float*)d_in[1];
    const float* position = (const float*)d_in[2];
    const float* scene    = (const float*)d_in[3];
    const int*   ntt      = (const int*)d_in[4];
    const float* Wv       = (const float*)d_in[5];
    const float* bv       = (const float*)d_in[6];
    const float* Ws       = (const float*)d_in[7];
    const float* bs       = (const float*)d_in[8];
    float* out = (float*)d_out;
    int nb = in_sizes[4];

    hw_bin_kernel<<<NBLK_HW + NBLK_BIN, 256>>>(hidden, Ws, position, ntt,
                                               scene, velocity, Wv, bv, out, nb);
    gather_kernel<<<M_ROWS, 192>>>(bs, out);
}

// round 17
// speedup vs baseline: 1.3155x; 1.0822x over previous
#include <cuda_runtime.h>
#include <cuda_fp16.h>
#include <cstdint>

#define NA 1024
#define NC 6
#define HH 48
#define NB_BINS 36
#define K_SP 1728          // 36*48
#define CE 64
#define VFC 16
#define OUT_C 128          // 64 + 16 + 48
#define M_ROWS (NA * NC)   // 6144
#define MAXE 512           // max supported episode size

// ---- device scratch -------------------------------------------------------
__device__ __half g_hw[M_ROWS * K_SP];     // hW[row, bin*48+n]  (fp16)
__device__ int2   g_desc[M_ROWS * MAXE];   // per (row, agent): (offset, w bits)
__device__ int    g_esz[M_ROWS];           // episode size per row

// ---- tf32 helpers ---------------------------------------------------------
__device__ __forceinline__ uint32_t to_tf32(float x) {
    uint32_t y; asm("cvt.rna.tf32.f32 %0, %1;" : "=r"(y) : "f"(x)); return y;
}
__device__ __forceinline__ void mma_tf32(float4& d,
    uint32_t a0, uint32_t a1, uint32_t a2, uint32_t a3,
    uint32_t b0, uint32_t b1)
{
    asm volatile(
        "mma.sync.aligned.m16n8k8.row.col.f32.tf32.tf32.f32 "
        "{%0,%1,%2,%3}, {%4,%5,%6,%7}, {%8,%9}, {%0,%1,%2,%3};"
        : "+f"(d.x), "+f"(d.y), "+f"(d.z), "+f"(d.w)
        : "r"(a0), "r"(a1), "r"(a2), "r"(a3), "r"(b0), "r"(b1));
}

// ---------------------------------------------------------------------------
// Kernel 1 (combined):
//   blocks [0, 288)        = tensor role: one (m-tile, bin-group-of-6);
//                            A staged+hoisted ONCE, 6x {stage B, mma, write}
//   blocks [288, 288+768)  = bin role: 8 rows each (32 lanes/row)
// ---------------------------------------------------------------------------
#define PM 128
#define SSTRIDE 52            // smem row stride (words); conflict-free frags
#define BINS_PER_TBLK 6
#define NBLK_T ((M_ROWS / PM) * (NB_BINS / BINS_PER_TBLK))   // 48*6 = 288
#define ROWS_PER_BINBLK 8
#define NBLK_BIN (M_ROWS / ROWS_PER_BINBLK)                  // 768
#define HW_SMEM_BYTES ((PM * SSTRIDE + HH * SSTRIDE) * 4)    // 36608

__global__ void __launch_bounds__(256) hw_bin_kernel(
    const float* __restrict__ hidden,     // [M_ROWS, 48]
    const float* __restrict__ Ws,         // [1728, 48]
    const float* __restrict__ position,   // [M_ROWS, 2]
    const int*   __restrict__ ntt,        // [nb]
    const float* __restrict__ scene,      // [M_ROWS, 64]
    const float* __restrict__ velocity,   // [M_ROWS, 2]
    const float* __restrict__ Wv,         // [2, 16]
    const float* __restrict__ bv,         // [16]
    float* __restrict__ out,              // [M_ROWS, 128]
    int nb)
{
    __shared__ __align__(16) char sraw[HW_SMEM_BYTES];
    const int tid = threadIdx.x;

    if (blockIdx.x < NBLK_T) {
        // ------------- tensor role: tf32 mma, 6 bins per block -------------
        uint32_t (*As)[SSTRIDE] = (uint32_t(*)[SSTRIDE])sraw;                    // [128][52]
        uint32_t (*Bs)[SSTRIDE] = (uint32_t(*)[SSTRIDE])(sraw + PM * SSTRIDE * 4); // [48][52]

        const int m0   = (blockIdx.x % (M_ROWS / PM)) * PM;
        const int bin0 = (blockIdx.x / (M_ROWS / PM)) * BINS_PER_TBLK;

        // stage A [128 x 48] once (tf32-rounded bits)
        for (int l = tid; l < PM * (HH / 4); l += 256) {
            int row = l / (HH / 4);
            int q   = (l % (HH / 4)) * 4;
            float4 v = *(const float4*)&hidden[(m0 + row) * HH + q];
            As[row][q + 0] = to_tf32(v.x);
            As[row][q + 1] = to_tf32(v.y);
            As[row][q + 2] = to_tf32(v.z);
            As[row][q + 3] = to_tf32(v.w);
        }
        __syncthreads();

        const int w    = tid / 32;        // warp 0..7 -> rows w*16..w*16+15
        const int lane = tid % 32;
        const int r    = lane >> 2;       // 0..7
        const int cc   = lane & 3;        // 0..3
        const int w16  = w * 16;

        // hoist all 6 A k-fragments once (24 regs)
        uint32_t af[6][4];
#pragma unroll
        for (int t = 0; t < 6; t++) {
            af[t][0] = As[w16 + r    ][8 * t + cc    ];
            af[t][1] = As[w16 + r + 8][8 * t + cc    ];
            af[t][2] = As[w16 + r    ][8 * t + cc + 4];
            af[t][3] = As[w16 + r + 8][8 * t + cc + 4];
        }

        for (int bi = 0; bi < BINS_PER_TBLK; bi++) {
            const int bin = bin0 + bi;
            // stage B block (tf32-rounded bits)
            for (int l = tid; l < HH * (HH / 4); l += 256) {
                int k = l / (HH / 4);
                int q = (l % (HH / 4)) * 4;
                float4 v = *(const float4*)&Ws[(bin * HH + k) * HH + q];
                Bs[k][q + 0] = to_tf32(v.x);
                Bs[k][q + 1] = to_tf32(v.y);
                Bs[k][q + 2] = to_tf32(v.z);
                Bs[k][q + 3] = to_tf32(v.w);
            }
            __syncthreads();

#pragma unroll
            for (int j = 0; j < 6; j++) {     // n-tiles of 8
                float4 d = make_float4(0.f, 0.f, 0.f, 0.f);
#pragma unroll
                for (int t = 0; t < 6; t++) { // k-tiles of 8
                    uint32_t b0 = Bs[8 * t + cc    ][8 * j + r];
                    uint32_t b1 = Bs[8 * t + cc + 4][8 * j + r];
                    mma_tf32(d, af[t][0], af[t][1], af[t][2], af[t][3], b0, b1);
                }
                // write D fragment as fp16 pairs
                int colb = bin * HH + 8 * j + 2 * cc;   // even -> 4B aligned
                *(__half2*)&g_hw[(m0 + w16 + r    ) * K_SP + colb] =
                    __floats2half2_rn(d.x, d.y);
                *(__half2*)&g_hw[(m0 + w16 + r + 8) * K_SP + colb] =
                    __floats2half2_rn(d.z, d.w);
            }
            __syncthreads();   // protect Bs before next stage
        }
    } else {
        // ------------- binning + concat role: 8 rows per block -------------
        int*   s_bin = (int*)sraw;                                   // [8][MAXE]
        int*   s_cnt = (int*)(sraw + 8 * MAXE * 4);                  // [8][36]
        float* s_inv = (float*)(sraw + 8 * MAXE * 4 + 8 * NB_BINS * 4);

        const int base = (int)(blockIdx.x - NBLK_T) * ROWS_PER_BINBLK;
        const int sub  = tid / 32;        // 0..7
        const int lane = tid % 32;
        const int row  = base + sub;
        const int a = row / NC;
        const int c = row % NC;

        if (lane == 0)
            for (int i = 0; i < NB_BINS; i++) s_cnt[sub * NB_BINS + i] = 0;

        int start = 0, end = 0, cum = 0;
        for (int i = 0; i < nb; i++) {
            int s = ntt[i];
            if (a >= cum && a < cum + s) { start = cum; end = cum + s; }
            cum += s;
        }
        int esz = end - start;
        if (esz > MAXE) esz = MAXE;

        const float px = position[row * 2 + 0];
        const float py = position[row * 2 + 1];
        const float rlogf = 0.34657359027997264f;
        const float PIf   = 3.14159265358979323846f;

        // fused concat: scene cols [0,64)
        for (int l = lane; l < CE; l += 32)
            out[row * OUT_C + l] = scene[row * CE + l];
        // velocity encoder cols [64,80)
        if (lane < VFC) {
            float v = velocity[row * 2 + 0] * Wv[lane]
                    + velocity[row * 2 + 1] * Wv[VFC + lane] + bv[lane];
            out[row * OUT_C + CE + lane] = fmaxf(v, 0.0f);
        }

        __syncthreads();

        for (int b = lane; b < esz; b += 32) {
            int brow = (start + b) * NC + c;
            float xd = px - position[brow * 2 + 0];
            float yd = py - position[brow * 2 + 1];
            float dist = sqrtf(xd * xd + yd * yd);
            int ring = (int)floorf(logf(dist / 0.5f + 1e-6f) / rlogf);
            int bin = -1;
            if (ring >= 0 && ring < 6) {
                float theta = atan2f(yd, xd);
                int wedge = (int)floorf((theta + PIf - 1e-6f) / PIf / 2.0f * 6.0f);
                bin = ring * 6 + wedge;
                if (bin < 0 || bin >= NB_BINS) bin = -1;
            }
            s_bin[sub * MAXE + b] = bin;
            if (bin >= 0) atomicAdd(&s_cnt[sub * NB_BINS + bin], 1);
        }
        __syncthreads();
        for (int i = lane; i < NB_BINS; i += 32)
            s_inv[sub * NB_BINS + i] =
                1.0f / (float)max(s_cnt[sub * NB_BINS + i], 1);
        __syncthreads();

        for (int b = lane; b < esz; b += 32) {
            int bin = s_bin[sub * MAXE + b];
            int off = ((start + b) * NC + c) * K_SP + max(bin, 0) * HH;
            float w = (bin >= 0) ? s_inv[sub * NB_BINS + bin] : 0.0f;
            g_desc[row * MAXE + b] = make_int2(off, __float_as_int(w));
        }
        if (lane == 0) g_esz[row] = esz;
    }
}

// ---------------------------------------------------------------------------
// Kernel 2: slim gather — descriptors -> smem, 16 groups x 12 threads x
// 4 cols; fp16 loads (uint2 = 4 halves), fp32 accumulate.
// ---------------------------------------------------------------------------
__global__ void __launch_bounds__(192) gather_kernel(
    const float* __restrict__ bs,         // [48]
    float* __restrict__ out)              // [M_ROWS, 128]
{
    const int row = blockIdx.x;
    const int tid = threadIdx.x;

    __shared__ int2  s_ow[MAXE];
    __shared__ float s_red[16][HH];

    const int esz = g_esz[row];
    for (int l = tid; l < esz; l += 192)
        s_ow[l] = g_desc[row * MAXE + l];
    __syncthreads();

    const int g  = tid / 12;              // 0..15
    const int n0 = (tid % 12) * 4;        // 8B-aligned half quad
    float4 acc0 = make_float4(0.f, 0.f, 0.f, 0.f);
    float4 acc1 = make_float4(0.f, 0.f, 0.f, 0.f);
    int b = g;
    for (; b + 16 < esz; b += 32) {
        int2 q0 = s_ow[b];
        int2 q1 = s_ow[b + 16];
        uint2 r0 = *(const uint2*)&g_hw[q0.x + n0];
        uint2 r1 = *(const uint2*)&g_hw[q1.x + n0];
        float w0 = __int_as_float(q0.y);
        float w1 = __int_as_float(q1.y);
        float2 f00 = __half22float2(*(__half2*)&r0.x);
        float2 f01 = __half22float2(*(__half2*)&r0.y);
        float2 f10 = __half22float2(*(__half2*)&r1.x);
        float2 f11 = __half22float2(*(__half2*)&r1.y);
        acc0.x += f00.x * w0; acc0.y += f00.y * w0;
        acc0.z += f01.x * w0; acc0.w += f01.y * w0;
        acc1.x += f10.x * w1; acc1.y += f10.y * w1;
        acc1.z += f11.x * w1; acc1.w += f11.y * w1;
    }
    for (; b < esz; b += 16) {
        int2 q = s_ow[b];
        uint2 rr = *(const uint2*)&g_hw[q.x + n0];
        float w = __int_as_float(q.y);
        float2 f0 = __half22float2(*(__half2*)&rr.x);
        float2 f1 = __half22float2(*(__half2*)&rr.y);
        acc0.x += f0.x * w; acc0.y += f0.y * w;
        acc0.z += f1.x * w; acc0.w += f1.y * w;
    }
    s_red[g][n0 + 0] = acc0.x + acc1.x;
    s_red[g][n0 + 1] = acc0.y + acc1.y;
    s_red[g][n0 + 2] = acc0.z + acc1.z;
    s_red[g][n0 + 3] = acc0.w + acc1.w;
    __syncthreads();

    if (tid < HH) {
        float t = 0.0f;
#pragma unroll
        for (int p = 0; p < 16; p++) t += s_red[p][tid];
        out[row * OUT_C + CE + VFC + tid] = fmaxf(t + bs[tid], 0.0f);
    }
}

// ---------------------------------------------------------------------------
extern "C" void kernel_launch(void* const* d_in, const int* in_sizes, int n_in,
                              void* d_out, int out_size)
{
    const float* hidden   = (const float*)d_in[0];
    const float* velocity = (const float*)d_in[1];
    const float* position = (const float*)d_in[2];
    const float* scene    = (const float*)d_in[3];
    const int*   ntt      = (const int*)d_in[4];
    const float* Wv       = (const float*)d_in[5];
    const float* bv       = (const float*)d_in[6];
    const float* Ws       = (const float*)d_in[7];
    const float* bs       = (const float*)d_in[8];
    float* out = (float*)d_out;
    int nb = in_sizes[4];

    hw_bin_kernel<<<NBLK_T + NBLK_BIN, 256>>>(hidden, Ws, position, ntt,
                                              scene, velocity, Wv, bv, out, nb);
    gather_kernel<<<M_ROWS, 192>>>(bs, out);
}